// round 12
// baseline (speedup 1.0000x reference)
#include <cuda_runtime.h>
#include <cuda_bf16.h>
#include <cuda_fp16.h>
#include <math.h>
#include <stdint.h>

#define NPTS  32768
#define NEDGE 786432
#define CIN   16
#define CMID  64
#define COUT  64
#define KMAX  64

// ---------------- device scratch ----------------
__device__ __half g_P_h[(size_t)NPTS * 1024];
__device__ __half g_W3T_hi[COUT * 1024];
__device__ __half g_W3T_lo[COUT * 1024];
__device__ int g_start[NPTS + 1];

// branchless CELU in fp32
__device__ __forceinline__ float celu_fast(float x) {
    return fmaxf(x, 0.0f) - 1.0f + __expf(fminf(x, 0.0f));
}
__device__ __forceinline__ uint32_t smem_u32(const void* p) {
    uint32_t a;
    asm("{ .reg .u64 t; cvta.to.shared.u64 t, %1; cvt.u32.u64 %0, t; }" : "=r"(a) : "l"(p));
    return a;
}
__device__ __forceinline__ void cp16(uint32_t dst, const void* src) {
    asm volatile("cp.async.cg.shared.global [%0], [%1], 16;" :: "r"(dst), "l"(src) : "memory");
}
#define CP_COMMIT() asm volatile("cp.async.commit_group;" ::: "memory")
#define CP_WAIT(n)  asm volatile("cp.async.wait_group %0;" :: "n"(n) : "memory")
#define BAR_SYNC(id, cnt) asm volatile("bar.sync %0, %1;" :: "r"(id), "r"(cnt) : "memory")

#define LDMATRIX_X4(r0, r1, r2, r3, addr) \
    asm volatile("ldmatrix.sync.aligned.m8n8.x4.shared.b16 {%0,%1,%2,%3}, [%4];" \
                 : "=r"(r0), "=r"(r1), "=r"(r2), "=r"(r3) : "r"(addr))
#define LDMATRIX_X4_T(r0, r1, r2, r3, addr) \
    asm volatile("ldmatrix.sync.aligned.m8n8.x4.trans.shared.b16 {%0,%1,%2,%3}, [%4];" \
                 : "=r"(r0), "=r"(r1), "=r"(r2), "=r"(r3) : "r"(addr))

#define MMA_FP16(C, A, B0, B1) \
    asm volatile("mma.sync.aligned.m16n8k16.row.col.f32.f16.f16.f32 " \
        "{%0,%1,%2,%3}, {%4,%5,%6,%7}, {%8,%9}, {%0,%1,%2,%3};" \
        : "+f"((C)[0]), "+f"((C)[1]), "+f"((C)[2]), "+f"((C)[3]) \
        : "r"((A)[0]), "r"((A)[1]), "r"((A)[2]), "r"((A)[3]), "r"(B0), "r"(B1))

__device__ __forceinline__ uint32_t pack_half2(float a, float b) {
    __half2 h = __floats2half2_rn(a, b);
    return *(uint32_t*)&h;
}

// ---------------------------------------------------------------------------
// Kernel A: fused aux — offsets + W3 split
// ---------------------------------------------------------------------------
#define NB_OFF ((NEDGE + 255) / 256)
#define NB_W3  ((1024 * 64) / 256)

__global__ void aux_kernel(const int* __restrict__ oi, const float* __restrict__ W3) {
    if (blockIdx.x < NB_OFF) {
        int e = blockIdx.x * 256 + threadIdx.x;
        if (e >= NEDGE) return;
        int v = oi[e];
        if (e == 0) {
            for (int n = 0; n <= v; n++) g_start[n] = 0;
        } else {
            int p = oi[e - 1];
            for (int n = p + 1; n <= v; n++) g_start[n] = e;
        }
        if (e == NEDGE - 1) {
            for (int n = v + 1; n <= NPTS; n++) g_start[n] = NEDGE;
        }
    } else {
        int t = (blockIdx.x - NB_OFF) * 256 + threadIdx.x;
        int k = t >> 6, n = t & 63;
        float v = W3[t];
        __half hi = __float2half_rn(v);
        __half lo = __float2half_rn(v - __half2float(hi));
        g_W3T_hi[n * 1024 + k] = hi;
        g_W3T_lo[n * 1024 + k] = lo;
    }
}

// ---------------------------------------------------------------------------
// Kernel C: edge kernel — TWO warps per point (m-column split), 4 warps/CTA
// = 2 points/CTA. Named barriers per point.
// ---------------------------------------------------------------------------
#define PHP 48
#define PXP 144
#define PMP 144
#define WHP 48

__global__ __launch_bounds__(128) void edge_tc_kernel(
    const float* __restrict__ x_in,
    const float* __restrict__ pos_in,
    const float* __restrict__ pos_out,
    const int*   __restrict__ in_index,
    const float* __restrict__ W1,
    const float* __restrict__ W2)
{
    __shared__ __align__(16) float sW1[48];
    __shared__ __align__(16) char s_w2t[64 * WHP];
    __shared__ __align__(16) char s_h [2][64 * PHP];   // per point
    __shared__ __align__(16) char s_xT[2][16 * PXP];   // per point
    __shared__ __align__(16) char s_M [2][16 * PMP];   // per point (both warps write halves)

    const int tid  = threadIdx.x;
    const int warp = tid >> 5;
    const int lane = tid & 31;
    const int pt   = warp >> 1;     // point within CTA (0,1)
    const int wh   = warp & 1;      // m-half of the point (0,1)

    // ---- early loads before the CTA-wide sync ----
    const int n = blockIdx.x * 2 + pt;
    const int start = __ldg(g_start + n);
    const int cnt   = __ldg(g_start + n + 1) - start;
    const int nl    = cnt < KMAX ? cnt : KMAX;
    const int tiles = (nl + 15) >> 4;
    const int epad  = tiles * 16;
    const float inv = (cnt > 0) ? (1.0f / (float)cnt) : 0.0f;

    const float po0 = __ldg(pos_out + 3 * n + 0);
    const float po1 = __ldg(pos_out + 3 * n + 1);
    const float po2 = __ldg(pos_out + 3 * n + 2);

    const int e0 = wh * 32 + lane;                 // this lane's edge
    const int myidx = (e0 < nl) ? __ldg(in_index + start + e0) : -1;

    // ---- CTA-shared weight staging ----
    if (tid < 48) sW1[tid] = W1[tid];
    for (int i = tid; i < 1024; i += 128) {
        int c = i >> 6, nn = i & 63;
        *(__half*)&s_w2t[nn * WHP + c * 2] = __float2half_rn(W2[i]);
    }
    __syncthreads();

    // hoist this warp's W2^T fragments: n-rows [wh*32, wh*32+32)
    uint32_t bW2[2][4];
    {
        uint32_t rsel = (uint32_t)((lane & 7) + ((lane & 16) ? 8 : 0));
        uint32_t csel = (lane & 8) ? 16u : 0u;
        uint32_t b0 = smem_u32(s_w2t);
#pragma unroll
        for (int jj = 0; jj < 2; jj++) {
            int j = 2 * wh + jj;
            uint32_t a = (rsel + j * 16) * WHP + csel;
            LDMATRIX_X4(bW2[jj][0], bW2[jj][1], bW2[jj][2], bW2[jj][3], b0 + a);
        }
    }

    float P[16];
#pragma unroll
    for (int i = 0; i < 16; i++) P[i] = 0.0f;

    const uint32_t shB = smem_u32(s_h[pt]);
    const uint32_t sxB = smem_u32(s_xT[pt]);
    const uint32_t smB = smem_u32(s_M[pt]);
    const int barid = 1 + pt;

    // ---- prologue: each warp handles its 32 edges, one per lane ----
    if (e0 < epad) {
        float h[16], x[16];
        if (myidx >= 0) {
            float d0 = __ldg(pos_in + 3 * myidx + 0) - po0;
            float d1 = __ldg(pos_in + 3 * myidx + 1) - po1;
            float d2 = __ldg(pos_in + 3 * myidx + 2) - po2;
            const float4* xr = (const float4*)(x_in + (size_t)myidx * CIN);
            float4 v0 = __ldg(xr), v1 = __ldg(xr + 1), v2 = __ldg(xr + 2), v3 = __ldg(xr + 3);
#pragma unroll
            for (int c = 0; c < 16; c++) {
                float a = fmaf(d0, sW1[c], fmaf(d1, sW1[16 + c], d2 * sW1[32 + c]));
                h[c] = celu_fast(a);
            }
            x[0] = v0.x;  x[1] = v0.y;  x[2] = v0.z;  x[3] = v0.w;
            x[4] = v1.x;  x[5] = v1.y;  x[6] = v1.z;  x[7] = v1.w;
            x[8] = v2.x;  x[9] = v2.y;  x[10] = v2.z; x[11] = v2.w;
            x[12] = v3.x; x[13] = v3.y; x[14] = v3.z; x[15] = v3.w;
        } else {
#pragma unroll
            for (int c = 0; c < 16; c++) { h[c] = 0.0f; x[c] = 0.0f; }
        }
        uint32_t hp[8];
#pragma unroll
        for (int j = 0; j < 8; j++) hp[j] = pack_half2(h[2 * j], h[2 * j + 1]);
        *(uint4*)(s_h[pt] + (uint32_t)e0 * PHP)      = make_uint4(hp[0], hp[1], hp[2], hp[3]);
        *(uint4*)(s_h[pt] + (uint32_t)e0 * PHP + 16) = make_uint4(hp[4], hp[5], hp[6], hp[7]);
#pragma unroll
        for (int c = 0; c < 16; c++) {
            *(__half*)(s_xT[pt] + (uint32_t)c * PXP + e0 * 2) = __float2half_rn(x[c]);
        }
    }
    BAR_SYNC(barid, 64);

    const uint32_t aRowOff = (uint32_t)(lane & 15);
    const uint32_t aColB   = ((lane >> 4) & 1) * 16;
    const uint32_t tRow    = (uint32_t)((lane & 7) + (((lane >> 3) & 1) << 3));
    const uint32_t tCol    = ((lane >> 4) & 1) * 16;
    const int g = lane >> 2;
    const int q = lane & 3;

    for (int t = 0; t < tiles; t++) {
        // ---- GEMM1 (half): M[:, wh*32 : wh*32+32] = celu(H @ W2_half) ----
        {
            uint32_t a[4];
            LDMATRIX_X4(a[0], a[1], a[2], a[3],
                        shB + (t * 16 + aRowOff) * PHP + aColB);
#pragma unroll
            for (int jj = 0; jj < 2; jj++) {
#pragma unroll
                for (int sub = 0; sub < 2; sub++) {
                    const int nt = 4 * wh + 2 * jj + sub;   // global 8-col block
                    float C1[4] = {0.f, 0.f, 0.f, 0.f};
                    MMA_FP16(C1, a, bW2[jj][2 * sub], bW2[jj][2 * sub + 1]);
                    const uint32_t cb = (uint32_t)(nt * 16 + q * 4);
#pragma unroll
                    for (int r2 = 0; r2 < 2; r2++) {
                        float v0 = celu_fast(C1[2 * r2]);
                        float v1 = celu_fast(C1[2 * r2 + 1]);
                        *(uint32_t*)(s_M[pt] + (uint32_t)(g + 8 * r2) * PMP + cb) =
                            pack_half2(v0, v1);
                    }
                }
            }
        }
        BAR_SYNC(barid, 64);

        // ---- GEMM2 (half): P[:, half] += X^T @ M_half ----
        {
            uint32_t ax[4];
            LDMATRIX_X4(ax[0], ax[1], ax[2], ax[3],
                        sxB + aRowOff * PXP + t * 32 + aColB);
#pragma unroll
            for (int pp = 0; pp < 2; pp++) {
                uint32_t b0, b1, b2, b3;
                LDMATRIX_X4_T(b0, b1, b2, b3,
                              smB + tRow * PMP + wh * 64 + pp * 32 + tCol);
                MMA_FP16(P + (2 * pp) * 4,     ax, b0, b1);
                MMA_FP16(P + (2 * pp + 1) * 4, ax, b2, b3);
            }
        }
        BAR_SYNC(barid, 64);
    }

    // ---- store this warp's m-half of P * inv ----
    __half* dp = g_P_h + (size_t)n * 1024;
#pragma unroll
    for (int l = 0; l < 4; l++) {
#pragma unroll
        for (int r2 = 0; r2 < 2; r2++) {
            int c = g + 8 * r2;
            int m = wh * 32 + l * 8 + 2 * q;
            *(uint32_t*)(dp + c * 64 + m) =
                pack_half2(P[l * 4 + 2 * r2] * inv, P[l * 4 + 2 * r2 + 1] * inv);
        }
    }
}

// ---------------------------------------------------------------------------
// Kernel D: out = P @ W3 + b3. Grid 512 = 256 M-tiles x 2 N-halves.
// M=128/CTA, N=32/CTA, 256 thr, 3-stage cp.async (15KB stages).
// ---------------------------------------------------------------------------
#define PITCH_B 80
#define OFF_A   0
#define OFF_BHI 10240
#define OFF_BLO 12800
#define STAGE_BYTES 15360
#define GEMM_SMEM (3 * STAGE_BYTES)

__global__ __launch_bounds__(256) void gemm_mma(
    const float* __restrict__ b3,
    float* __restrict__ out)
{
    extern __shared__ char dsm[];
    const uint32_t sbase = smem_u32(dsm);

    const int tid  = threadIdx.x;
    const int warp = tid >> 5;
    const int lane = tid & 31;
    const int mt   = blockIdx.x >> 1;
    const int nh   = blockIdx.x & 1;
    const int ctaM = mt * 128;
    const int ctaN = nh * 32;

    const char* A_g   = (const char*)(g_P_h + (size_t)ctaM * 1024);
    const char* Bhi_g = (const char*)(g_W3T_hi + (size_t)ctaN * 1024);
    const char* Blo_g = (const char*)(g_W3T_lo + (size_t)ctaN * 1024);

    auto issue_loads = [&](int kt, int s) {
        uint32_t base = sbase + s * STAGE_BYTES;
        const int kb = kt * 64;
#pragma unroll
        for (int i = 0; i < 2; i++) {
            int idx = tid + i * 256;              // A: 128 rows x 4 segs
            int row = idx >> 2, seg = idx & 3;
            uint32_t d = base + OFF_A + row * PITCH_B + seg * 16;
            cp16(d, A_g + (size_t)row * 2048 + kb + seg * 16);
        }
        {
            // B: 32 rows x 4 segs x {hi,lo} = 256 items, one per thread
            int half = tid >> 7;                  // 0 = hi, 1 = lo
            int r    = tid & 127;
            int row = r >> 2, seg = r & 3;
            const char* Bg = half ? Blo_g : Bhi_g;
            uint32_t off = half ? OFF_BLO : OFF_BHI;
            uint32_t d = base + off + row * PITCH_B + seg * 16;
            cp16(d, Bg + (size_t)row * 2048 + kb + seg * 16);
        }
    };

    float C[4][4];
#pragma unroll
    for (int nt = 0; nt < 4; nt++)
#pragma unroll
        for (int i = 0; i < 4; i++) C[nt][i] = 0.0f;

    const uint32_t aRow  = warp * 16 + (lane & 15);
    const uint32_t aColB = ((lane >> 4) & 1) * 16;
    const uint32_t bRow  = (lane & 7) + ((lane & 16) ? 8 : 0);
    const uint32_t bColB = (lane & 8) ? 16 : 0;

    issue_loads(0, 0); CP_COMMIT();
    issue_loads(1, 1); CP_COMMIT();

    int scur = 0;
    for (int kt = 0; kt < 32; kt++) {
        CP_WAIT(1);
        __syncthreads();
        if (kt + 2 < 32) {
            int snext = scur + 2; if (snext >= 3) snext -= 3;
            issue_loads(kt + 2, snext);
        }
        CP_COMMIT();

        const uint32_t base = sbase + scur * STAGE_BYTES;
#pragma unroll
        for (int ks = 0; ks < 2; ks++) {
            const uint32_t kOffB = ks * 32;
            uint32_t a[4];
            LDMATRIX_X4(a[0], a[1], a[2], a[3],
                        base + OFF_A + aRow * PITCH_B + kOffB + aColB);
#pragma unroll
            for (int p = 0; p < 2; p++) {
                uint32_t bh0, bh1, bh2, bh3, bl0, bl1, bl2, bl3;
                uint32_t ba = base + (p * 16 + bRow) * PITCH_B + kOffB + bColB;
                LDMATRIX_X4(bh0, bh1, bh2, bh3, ba + OFF_BHI);
                LDMATRIX_X4(bl0, bl1, bl2, bl3, ba + OFF_BLO);
                MMA_FP16(C[2 * p],     a, bh0, bh1);
                MMA_FP16(C[2 * p],     a, bl0, bl1);
                MMA_FP16(C[2 * p + 1], a, bh2, bh3);
                MMA_FP16(C[2 * p + 1], a, bl2, bl3);
            }
        }
        if (++scur == 3) scur = 0;
    }

    const int g  = lane >> 2;
    const int q2 = (lane & 3) * 2;
    const int rowBase = ctaM + warp * 16;
#pragma unroll
    for (int nt = 0; nt < 4; nt++) {
        const int col = ctaN + nt * 8 + q2;
        float2 bb = *(const float2*)(b3 + col);
        float2 v0, v1;
        v0.x = C[nt][0] + bb.x;
        v0.y = C[nt][1] + bb.y;
        v1.x = C[nt][2] + bb.x;
        v1.y = C[nt][3] + bb.y;
        *(float2*)(out + (size_t)(rowBase + g) * COUT + col) = v0;
        *(float2*)(out + (size_t)(rowBase + g + 8) * COUT + col) = v1;
    }
}

// ---------------------------------------------------------------------------
extern "C" void kernel_launch(void* const* d_in, const int* in_sizes, int n_in,
                              void* d_out, int out_size) {
    const float* x_in      = (const float*)d_in[0];
    const float* pos_in    = (const float*)d_in[1];
    const float* pos_out   = (const float*)d_in[2];
    const int*   in_index  = (const int*)d_in[3];
    const int*   out_index = (const int*)d_in[4];
    const float* W1        = (const float*)d_in[5];
    const float* W2        = (const float*)d_in[6];
    const float* W3        = (const float*)d_in[7];
    const float* b3        = (const float*)d_in[8];
    float* out = (float*)d_out;

    cudaFuncSetAttribute(gemm_mma, cudaFuncAttributeMaxDynamicSharedMemorySize, GEMM_SMEM);

    aux_kernel<<<NB_OFF + NB_W3, 256>>>(out_index, W3);
    edge_tc_kernel<<<NPTS / 2, 128>>>(x_in, pos_in, pos_out, in_index, W1, W2);
    gemm_mma<<<(NPTS / 128) * 2, 256, GEMM_SMEM>>>(b3, out);
}

// round 13
// speedup vs baseline: 1.3770x; 1.3770x over previous
#include <cuda_runtime.h>
#include <cuda_bf16.h>
#include <cuda_fp16.h>
#include <math.h>
#include <stdint.h>

#define NPTS  32768
#define NEDGE 786432
#define CIN   16
#define CMID  64
#define COUT  64
#define KMAX  64

// ---------------- device scratch ----------------
// NOTE: k-index of P and W3T is REORDERED: k' = m*16 + c  (m in [0,64), c in [0,16))
__device__ __half g_P_h[(size_t)NPTS * 1024];
__device__ __half g_W3T_hi[COUT * 1024];
__device__ __half g_W3T_lo[COUT * 1024];
__device__ int g_start[NPTS + 1];

// branchless CELU in fp32 (same arithmetic as R11)
__device__ __forceinline__ float celu_fast(float x) {
    return fmaxf(x, 0.0f) - 1.0f + __expf(fminf(x, 0.0f));
}
__device__ __forceinline__ uint32_t smem_u32(const void* p) {
    uint32_t a;
    asm("{ .reg .u64 t; cvta.to.shared.u64 t, %1; cvt.u32.u64 %0, t; }" : "=r"(a) : "l"(p));
    return a;
}
__device__ __forceinline__ void cp16(uint32_t dst, const void* src) {
    asm volatile("cp.async.cg.shared.global [%0], [%1], 16;" :: "r"(dst), "l"(src) : "memory");
}
#define CP_COMMIT() asm volatile("cp.async.commit_group;" ::: "memory")
#define CP_WAIT(n)  asm volatile("cp.async.wait_group %0;" :: "n"(n) : "memory")
#define PREFETCH_L2(p) asm volatile("prefetch.global.L2 [%0];" :: "l"(p))

#define LDMATRIX_X4(r0, r1, r2, r3, addr) \
    asm volatile("ldmatrix.sync.aligned.m8n8.x4.shared.b16 {%0,%1,%2,%3}, [%4];" \
                 : "=r"(r0), "=r"(r1), "=r"(r2), "=r"(r3) : "r"(addr))
#define LDMATRIX_X4_T(r0, r1, r2, r3, addr) \
    asm volatile("ldmatrix.sync.aligned.m8n8.x4.trans.shared.b16 {%0,%1,%2,%3}, [%4];" \
                 : "=r"(r0), "=r"(r1), "=r"(r2), "=r"(r3) : "r"(addr))

#define MMA_FP16(C, A, B0, B1) \
    asm volatile("mma.sync.aligned.m16n8k16.row.col.f32.f16.f16.f32 " \
        "{%0,%1,%2,%3}, {%4,%5,%6,%7}, {%8,%9}, {%0,%1,%2,%3};" \
        : "+f"((C)[0]), "+f"((C)[1]), "+f"((C)[2]), "+f"((C)[3]) \
        : "r"((A)[0]), "r"((A)[1]), "r"((A)[2]), "r"((A)[3]), "r"(B0), "r"(B1))

__device__ __forceinline__ uint32_t pack_half2(float a, float b) {
    __half2 h = __floats2half2_rn(a, b);
    return *(uint32_t*)&h;
}

// ---------------------------------------------------------------------------
// Kernel A: fused aux — offsets + W3 split with k-reorder (k' = m*16 + c)
// ---------------------------------------------------------------------------
#define NB_OFF ((NEDGE + 255) / 256)
#define NB_W3  ((1024 * 64) / 256)

__global__ void aux_kernel(const int* __restrict__ oi, const float* __restrict__ W3) {
    if (blockIdx.x < NB_OFF) {
        int e = blockIdx.x * 256 + threadIdx.x;
        if (e >= NEDGE) return;
        int v = oi[e];
        if (e == 0) {
            for (int n = 0; n <= v; n++) g_start[n] = 0;
        } else {
            int p = oi[e - 1];
            for (int n = p + 1; n <= v; n++) g_start[n] = e;
        }
        if (e == NEDGE - 1) {
            for (int n = v + 1; n <= NPTS; n++) g_start[n] = NEDGE;
        }
    } else {
        int t = (blockIdx.x - NB_OFF) * 256 + threadIdx.x;
        int k = t >> 6, n = t & 63;           // W3 row k = c*64 + m
        int c = k >> 6, m = k & 63;
        int kp = m * 16 + c;                  // reordered k
        float v = W3[t];
        __half hi = __float2half_rn(v);
        __half lo = __float2half_rn(v - __half2float(hi));
        g_W3T_hi[n * 1024 + kp] = hi;
        g_W3T_lo[n * 1024 + kp] = lo;
    }
}

// ---------------------------------------------------------------------------
// Kernel C: edge kernel — register-chained GEMMs. Warp per point, 4 warps/CTA.
//   GEMM1': M^T[64m x 16e] = W2^T(A) @ H^T(B)   (f32 acc, celu, pack -> A frags)
//   GEMM2': P^T[64m x 16c] += M^T(A) @ X(B)
// No smem round-trip for M; zero syncs in the tile loop.
// ---------------------------------------------------------------------------
#define PHP 48     // s_x pitch:  [e][c], 32B data + pad
#define PXP 144    // s_hT pitch: [c][e], 128B data + pad
#define WHP 48     // s_w2t pitch: [m][c]

__global__ __launch_bounds__(128) void edge_tc_kernel(
    const float* __restrict__ x_in,
    const float* __restrict__ pos_in,
    const float* __restrict__ pos_out,
    const int*   __restrict__ in_index,
    const float* __restrict__ W1,
    const float* __restrict__ W2)
{
    __shared__ __align__(16) float sW1[48];
    __shared__ __align__(16) char s_w2t[64 * WHP];      // W2^T: [m][c] fp16
    __shared__ __align__(16) char s_hT [4][16 * PXP];   // H^T: [c][e] fp16 (e up to 64)
    __shared__ __align__(16) char s_x  [4][64 * PHP];   // X:   [e][c] fp16

    const int tid  = threadIdx.x;
    const int warp = tid >> 5;
    const int lane = tid & 31;

    // ---- early loads before CTA-wide sync ----
    const int n = blockIdx.x * 4 + warp;
    const int start = __ldg(g_start + n);
    const int cnt   = __ldg(g_start + n + 1) - start;
    const int nl    = cnt < KMAX ? cnt : KMAX;
    const int tiles = (nl + 15) >> 4;
    const int epad  = tiles * 16;
    const float inv = (cnt > 0) ? (1.0f / (float)cnt) : 0.0f;

    const float po0 = __ldg(pos_out + 3 * n + 0);
    const float po1 = __ldg(pos_out + 3 * n + 1);
    const float po2 = __ldg(pos_out + 3 * n + 2);

    int myidx[2];
#pragma unroll
    for (int it = 0; it < 2; it++) {
        int e = lane + 32 * it;
        myidx[it] = (e < nl) ? __ldg(in_index + start + e) : -1;
    }

    // ---- CTA-shared weight staging ----
    if (tid < 48) sW1[tid] = W1[tid];
    for (int i = tid; i < 1024; i += 128) {
        int c = i >> 6, m = i & 63;
        *(__half*)&s_w2t[m * WHP + c * 2] = __float2half_rn(W2[i]);   // W2[c][m] -> [m][c]
    }
    __syncthreads();

    // hoist W2^T A-fragments (row-major m16 x k16 tiles)
    uint32_t aW2[4][4];
    {
        uint32_t rowOff = (uint32_t)(lane & 15);
        uint32_t colB   = ((lane >> 4) & 1) * 16;
        uint32_t b0 = smem_u32(s_w2t);
#pragma unroll
        for (int mt = 0; mt < 4; mt++) {
            uint32_t a = (mt * 16 + rowOff) * WHP + colB;
            LDMATRIX_X4(aW2[mt][0], aW2[mt][1], aW2[mt][2], aW2[mt][3], b0 + a);
        }
    }

    float P[32];
#pragma unroll
    for (int i = 0; i < 32; i++) P[i] = 0.0f;

    const uint32_t shB = smem_u32(s_hT[warp]);
    const uint32_t sxB = smem_u32(s_x[warp]);

    // ---- prologue: one lane per edge; H -> [c][e], X -> [e][c] ----
#pragma unroll
    for (int it = 0; it < 2; it++) {
        const int e = lane + 32 * it;
        if (e >= epad) break;
        float h[16], x[16];
        const int idx = myidx[it];
        if (idx >= 0) {
            float d0 = __ldg(pos_in + 3 * idx + 0) - po0;
            float d1 = __ldg(pos_in + 3 * idx + 1) - po1;
            float d2 = __ldg(pos_in + 3 * idx + 2) - po2;
            const float4* xr = (const float4*)(x_in + (size_t)idx * CIN);
            float4 v0 = __ldg(xr), v1 = __ldg(xr + 1), v2 = __ldg(xr + 2), v3 = __ldg(xr + 3);
#pragma unroll
            for (int c = 0; c < 16; c++) {
                float a = fmaf(d0, sW1[c], fmaf(d1, sW1[16 + c], d2 * sW1[32 + c]));
                h[c] = celu_fast(a);
            }
            x[0] = v0.x;  x[1] = v0.y;  x[2] = v0.z;  x[3] = v0.w;
            x[4] = v1.x;  x[5] = v1.y;  x[6] = v1.z;  x[7] = v1.w;
            x[8] = v2.x;  x[9] = v2.y;  x[10] = v2.z; x[11] = v2.w;
            x[12] = v3.x; x[13] = v3.y; x[14] = v3.z; x[15] = v3.w;
        } else {
#pragma unroll
            for (int c = 0; c < 16; c++) { h[c] = 0.0f; x[c] = 0.0f; }
        }
        // H^T: scattered b16 stores into [c][e]
#pragma unroll
        for (int c = 0; c < 16; c++) {
            *(__half*)(s_hT[warp] + (uint32_t)c * PXP + e * 2) = __float2half_rn(h[c]);
        }
        // X: contiguous row [e][c]
        uint32_t xp[8];
#pragma unroll
        for (int j = 0; j < 8; j++) xp[j] = pack_half2(x[2 * j], x[2 * j + 1]);
        *(uint4*)(s_x[warp] + (uint32_t)e * PHP)      = make_uint4(xp[0], xp[1], xp[2], xp[3]);
        *(uint4*)(s_x[warp] + (uint32_t)e * PHP + 16) = make_uint4(xp[4], xp[5], xp[6], xp[7]);
    }
    __syncwarp();

    const uint32_t tRow = (uint32_t)((lane & 7) + (((lane >> 3) & 1) << 3));
    const uint32_t tCol = ((lane >> 4) & 1) * 16;
    const int g = lane >> 2;
    const int q = lane & 3;

    for (int t = 0; t < tiles; t++) {
        // B frags: H^T (k=c, n=e of this tile) and X (k=e of this tile, n=c)
        uint32_t bH[4], bX[4];
        LDMATRIX_X4_T(bH[0], bH[1], bH[2], bH[3], shB + tRow * PXP + t * 32 + tCol);
        LDMATRIX_X4_T(bX[0], bX[1], bX[2], bX[3], sxB + (t * 16 + tRow) * PHP + tCol);

#pragma unroll
        for (int mt = 0; mt < 4; mt++) {
            // GEMM1': M^T tile (m16 x e16) in f32
            float C1a[4] = {0.f, 0.f, 0.f, 0.f};
            float C1b[4] = {0.f, 0.f, 0.f, 0.f};
            MMA_FP16(C1a, aW2[mt], bH[0], bH[1]);   // e 0..7
            MMA_FP16(C1b, aW2[mt], bH[2], bH[3]);   // e 8..15
            // celu + pack straight into A-fragment layout
            uint32_t aM[4];
            aM[0] = pack_half2(celu_fast(C1a[0]), celu_fast(C1a[1]));
            aM[1] = pack_half2(celu_fast(C1a[2]), celu_fast(C1a[3]));
            aM[2] = pack_half2(celu_fast(C1b[0]), celu_fast(C1b[1]));
            aM[3] = pack_half2(celu_fast(C1b[2]), celu_fast(C1b[3]));
            // GEMM2': P^T tile += M^T @ X
            MMA_FP16(P + mt * 8,     aM, bX[0], bX[1]);   // c 0..7
            MMA_FP16(P + mt * 8 + 4, aM, bX[2], bX[3]);   // c 8..15
        }
    }

    // ---- store P^T * inv with k' = m*16 + c ordering (coalesced STG.b32) ----
    __half* dp = g_P_h + (size_t)n * 1024;
#pragma unroll
    for (int mt = 0; mt < 4; mt++) {
#pragma unroll
        for (int ch = 0; ch < 2; ch++) {
#pragma unroll
            for (int r2 = 0; r2 < 2; r2++) {
                float v0 = P[mt * 8 + ch * 4 + 2 * r2]     * inv;
                float v1 = P[mt * 8 + ch * 4 + 2 * r2 + 1] * inv;
                int m = mt * 16 + g + 8 * r2;
                int c = ch * 8 + 2 * q;
                *(uint32_t*)(dp + m * 16 + c) = pack_half2(v0, v1);
            }
        }
    }
}

// ---------------------------------------------------------------------------
// Kernel D: out = P @ W3 + b3. M=128/CTA, 256 thr, 3-stage (R11 config).
// ---------------------------------------------------------------------------
#define PITCH_B 80
#define OFF_A   0
#define OFF_BHI 10240
#define OFF_BLO 15360
#define STAGE_BYTES 20480
#define GEMM_SMEM (3 * STAGE_BYTES)

__global__ __launch_bounds__(256) void gemm_mma(
    const float* __restrict__ b3,
    float* __restrict__ out)
{
    extern __shared__ char dsm[];
    const uint32_t sbase = smem_u32(dsm);

    const int tid  = threadIdx.x;
    const int warp = tid >> 5;
    const int lane = tid & 31;
    const int ctaM = blockIdx.x * 128;

    const char* A_g   = (const char*)(g_P_h + (size_t)ctaM * 1024);
    const char* Bhi_g = (const char*)g_W3T_hi;
    const char* Blo_g = (const char*)g_W3T_lo;

    auto issue_loads = [&](int kt, int s) {
        uint32_t base = sbase + s * STAGE_BYTES;
        const int kb = kt * 64;
#pragma unroll
        for (int i = 0; i < 2; i++) {
            int idx = tid + i * 256;
            int row = idx >> 2, seg = idx & 3;
            uint32_t d = base + OFF_A + row * PITCH_B + seg * 16;
            cp16(d, A_g + (size_t)row * 2048 + kb + seg * 16);
        }
        {
            int row = tid >> 2, seg = tid & 3;
            uint32_t d = base + row * PITCH_B + seg * 16;
            size_t gofs = (size_t)row * 2048 + kb + seg * 16;
            cp16(d + OFF_BHI, Bhi_g + gofs);
            cp16(d + OFF_BLO, Blo_g + gofs);
        }
    };

    float C[8][4];
#pragma unroll
    for (int nt = 0; nt < 8; nt++)
#pragma unroll
        for (int i = 0; i < 4; i++) C[nt][i] = 0.0f;

    const uint32_t aRow  = warp * 16 + (lane & 15);
    const uint32_t aColB = ((lane >> 4) & 1) * 16;
    const uint32_t bRow  = (lane & 7) + ((lane & 16) ? 8 : 0);
    const uint32_t bColB = (lane & 8) ? 16 : 0;

    if (tid < 128) {
#pragma unroll
        for (int pf = 0; pf < 6; pf++)
            PREFETCH_L2(A_g + (size_t)tid * 2048 + pf * 64);
    }

    issue_loads(0, 0); CP_COMMIT();
    issue_loads(1, 1); CP_COMMIT();

    int scur = 0;
    for (int kt = 0; kt < 32; kt++) {
        CP_WAIT(1);
        __syncthreads();
        if (kt + 2 < 32) {
            int snext = scur + 2; if (snext >= 3) snext -= 3;
            issue_loads(kt + 2, snext);
        }
        CP_COMMIT();
        if (kt + 6 < 32 && tid < 128)
            PREFETCH_L2(A_g + (size_t)tid * 2048 + (kt + 6) * 64);

        const uint32_t base = sbase + scur * STAGE_BYTES;
#pragma unroll
        for (int ks = 0; ks < 2; ks++) {
            const uint32_t kOffB = ks * 32;
            uint32_t a[4];
            LDMATRIX_X4(a[0], a[1], a[2], a[3],
                        base + OFF_A + aRow * PITCH_B + kOffB + aColB);
#pragma unroll
            for (int p = 0; p < 4; p++) {
                uint32_t bh0, bh1, bh2, bh3, bl0, bl1, bl2, bl3;
                uint32_t ba = base + (p * 16 + bRow) * PITCH_B + kOffB + bColB;
                LDMATRIX_X4(bh0, bh1, bh2, bh3, ba + OFF_BHI);
                LDMATRIX_X4(bl0, bl1, bl2, bl3, ba + OFF_BLO);
                MMA_FP16(C[2 * p],     a, bh0, bh1);
                MMA_FP16(C[2 * p],     a, bl0, bl1);
                MMA_FP16(C[2 * p + 1], a, bh2, bh3);
                MMA_FP16(C[2 * p + 1], a, bl2, bl3);
            }
        }
        if (++scur == 3) scur = 0;
    }

    const int g  = lane >> 2;
    const int q2 = (lane & 3) * 2;
    const int rowBase = ctaM + warp * 16;
#pragma unroll
    for (int nt = 0; nt < 8; nt++) {
        const int col = nt * 8 + q2;
        float2 bb = *(const float2*)(b3 + col);
        float2 v0, v1;
        v0.x = C[nt][0] + bb.x;
        v0.y = C[nt][1] + bb.y;
        v1.x = C[nt][2] + bb.x;
        v1.y = C[nt][3] + bb.y;
        *(float2*)(out + (size_t)(rowBase + g) * COUT + col) = v0;
        *(float2*)(out + (size_t)(rowBase + g + 8) * COUT + col) = v1;
    }
}

// ---------------------------------------------------------------------------
extern "C" void kernel_launch(void* const* d_in, const int* in_sizes, int n_in,
                              void* d_out, int out_size) {
    const float* x_in      = (const float*)d_in[0];
    const float* pos_in    = (const float*)d_in[1];
    const float* pos_out   = (const float*)d_in[2];
    const int*   in_index  = (const int*)d_in[3];
    const int*   out_index = (const int*)d_in[4];
    const float* W1        = (const float*)d_in[5];
    const float* W2        = (const float*)d_in[6];
    const float* W3        = (const float*)d_in[7];
    const float* b3        = (const float*)d_in[8];
    float* out = (float*)d_out;

    cudaFuncSetAttribute(gemm_mma, cudaFuncAttributeMaxDynamicSharedMemorySize, GEMM_SMEM);

    aux_kernel<<<NB_OFF + NB_W3, 256>>>(out_index, W3);
    edge_tc_kernel<<<NPTS / 4, 128>>>(x_in, pos_in, pos_out, in_index, W1, W2);
    gemm_mma<<<NPTS / 128, 256, GEMM_SMEM>>>(b3, out);
}

// round 14
// speedup vs baseline: 1.5897x; 1.1545x over previous
#include <cuda_runtime.h>
#include <cuda_bf16.h>
#include <cuda_fp16.h>
#include <math.h>
#include <stdint.h>

#define NPTS  32768
#define NEDGE 786432
#define CIN   16
#define CMID  64
#define COUT  64
#define KMAX  64

// ---------------- device scratch ----------------
// k-index of P and W3T is REORDERED: k' = m*16 + c
__device__ __half g_P_h[(size_t)NPTS * 1024];
__device__ __half g_W3T[COUT * 1024];       // single fp16
__device__ int g_start[NPTS + 1];

// branchless CELU in fp32
__device__ __forceinline__ float celu_fast(float x) {
    return fmaxf(x, 0.0f) - 1.0f + __expf(fminf(x, 0.0f));
}
__device__ __forceinline__ uint32_t smem_u32(const void* p) {
    uint32_t a;
    asm("{ .reg .u64 t; cvta.to.shared.u64 t, %1; cvt.u32.u64 %0, t; }" : "=r"(a) : "l"(p));
    return a;
}
__device__ __forceinline__ void cp16(uint32_t dst, const void* src) {
    asm volatile("cp.async.cg.shared.global [%0], [%1], 16;" :: "r"(dst), "l"(src) : "memory");
}
#define CP_COMMIT() asm volatile("cp.async.commit_group;" ::: "memory")
#define CP_WAIT(n)  asm volatile("cp.async.wait_group %0;" :: "n"(n) : "memory")

#define LDMATRIX_X4(r0, r1, r2, r3, addr) \
    asm volatile("ldmatrix.sync.aligned.m8n8.x4.shared.b16 {%0,%1,%2,%3}, [%4];" \
                 : "=r"(r0), "=r"(r1), "=r"(r2), "=r"(r3) : "r"(addr))
#define LDMATRIX_X4_T(r0, r1, r2, r3, addr) \
    asm volatile("ldmatrix.sync.aligned.m8n8.x4.trans.shared.b16 {%0,%1,%2,%3}, [%4];" \
                 : "=r"(r0), "=r"(r1), "=r"(r2), "=r"(r3) : "r"(addr))

#define MMA_FP16(C, A, B0, B1) \
    asm volatile("mma.sync.aligned.m16n8k16.row.col.f32.f16.f16.f32 " \
        "{%0,%1,%2,%3}, {%4,%5,%6,%7}, {%8,%9}, {%0,%1,%2,%3};" \
        : "+f"((C)[0]), "+f"((C)[1]), "+f"((C)[2]), "+f"((C)[3]) \
        : "r"((A)[0]), "r"((A)[1]), "r"((A)[2]), "r"((A)[3]), "r"(B0), "r"(B1))

__device__ __forceinline__ uint32_t pack_half2(float a, float b) {
    __half2 h = __floats2half2_rn(a, b);
    return *(uint32_t*)&h;
}

// ---------------------------------------------------------------------------
// Kernel A: fused aux — offsets + W3 fp16 with k-reorder (k' = m*16 + c)
// ---------------------------------------------------------------------------
#define NB_OFF ((NEDGE + 255) / 256)
#define NB_W3  ((1024 * 64) / 256)

__global__ void aux_kernel(const int* __restrict__ oi, const float* __restrict__ W3) {
    if (blockIdx.x < NB_OFF) {
        int e = blockIdx.x * 256 + threadIdx.x;
        if (e >= NEDGE) return;
        int v = oi[e];
        if (e == 0) {
            for (int n = 0; n <= v; n++) g_start[n] = 0;
        } else {
            int p = oi[e - 1];
            for (int n = p + 1; n <= v; n++) g_start[n] = e;
        }
        if (e == NEDGE - 1) {
            for (int n = v + 1; n <= NPTS; n++) g_start[n] = NEDGE;
        }
    } else {
        int t = (blockIdx.x - NB_OFF) * 256 + threadIdx.x;
        int k = t >> 6, n = t & 63;           // W3 row k = c*64 + m
        int c = k >> 6, m = k & 63;
        int kp = m * 16 + c;
        g_W3T[n * 1024 + kp] = __float2half_rn(W3[t]);
    }
}

// ---------------------------------------------------------------------------
// Kernel C: edge kernel — register-chained GEMMs, both operands staged as
// contiguous [e][c] rows. Warp per point, 4 warps/CTA.
//   GEMM1': M^T = W2^T(A) @ H^T(B)  — B via NON-trans ldmatrix of s_h[e][c]
//   GEMM2': P^T += M^T(A) @ X(B)    — B via trans ldmatrix of s_x[e][c]
// ---------------------------------------------------------------------------
#define PHP 48     // row pitch for s_h and s_x: [e][c], 32B data + 16 pad
#define WHP 48     // s_w2t pitch: [m][c]

__global__ __launch_bounds__(128) void edge_tc_kernel(
    const float* __restrict__ x_in,
    const float* __restrict__ pos_in,
    const float* __restrict__ pos_out,
    const int*   __restrict__ in_index,
    const float* __restrict__ W1,
    const float* __restrict__ W2)
{
    __shared__ __align__(16) float sW1[48];
    __shared__ __align__(16) char s_w2t[64 * WHP];
    __shared__ __align__(16) char s_h [4][64 * PHP];   // H: [e][c] fp16
    __shared__ __align__(16) char s_x [4][64 * PHP];   // X: [e][c] fp16

    const int tid  = threadIdx.x;
    const int warp = tid >> 5;
    const int lane = tid & 31;

    // ---- early loads before CTA-wide sync ----
    const int n = blockIdx.x * 4 + warp;
    const int start = __ldg(g_start + n);
    const int cnt   = __ldg(g_start + n + 1) - start;
    const int nl    = cnt < KMAX ? cnt : KMAX;
    const int tiles = (nl + 15) >> 4;
    const int epad  = tiles * 16;
    const float inv = (cnt > 0) ? (1.0f / (float)cnt) : 0.0f;

    const float po0 = __ldg(pos_out + 3 * n + 0);
    const float po1 = __ldg(pos_out + 3 * n + 1);
    const float po2 = __ldg(pos_out + 3 * n + 2);

    int myidx[2];
#pragma unroll
    for (int it = 0; it < 2; it++) {
        int e = lane + 32 * it;
        myidx[it] = (e < nl) ? __ldg(in_index + start + e) : -1;
    }

    // ---- CTA-shared weight staging ----
    if (tid < 48) sW1[tid] = W1[tid];
    for (int i = tid; i < 1024; i += 128) {
        int c = i >> 6, m = i & 63;
        *(__half*)&s_w2t[m * WHP + c * 2] = __float2half_rn(W2[i]);
    }
    __syncthreads();

    // hoist W2^T A-fragments
    uint32_t aW2[4][4];
    {
        uint32_t rowOff = (uint32_t)(lane & 15);
        uint32_t colB   = ((lane >> 4) & 1) * 16;
        uint32_t b0 = smem_u32(s_w2t);
#pragma unroll
        for (int mt = 0; mt < 4; mt++) {
            uint32_t a = (mt * 16 + rowOff) * WHP + colB;
            LDMATRIX_X4(aW2[mt][0], aW2[mt][1], aW2[mt][2], aW2[mt][3], b0 + a);
        }
    }

    float P[32];
#pragma unroll
    for (int i = 0; i < 32; i++) P[i] = 0.0f;

    const uint32_t shB = smem_u32(s_h[warp]);
    const uint32_t sxB = smem_u32(s_x[warp]);

    // ---- prologue: one lane per edge; both H and X as contiguous [e][c] ----
#pragma unroll
    for (int it = 0; it < 2; it++) {
        const int e = lane + 32 * it;
        if (e >= epad) break;
        float h[16], x[16];
        const int idx = myidx[it];
        if (idx >= 0) {
            float d0 = __ldg(pos_in + 3 * idx + 0) - po0;
            float d1 = __ldg(pos_in + 3 * idx + 1) - po1;
            float d2 = __ldg(pos_in + 3 * idx + 2) - po2;
            const float4* xr = (const float4*)(x_in + (size_t)idx * CIN);
            float4 v0 = __ldg(xr), v1 = __ldg(xr + 1), v2 = __ldg(xr + 2), v3 = __ldg(xr + 3);
#pragma unroll
            for (int c = 0; c < 16; c++) {
                float a = fmaf(d0, sW1[c], fmaf(d1, sW1[16 + c], d2 * sW1[32 + c]));
                h[c] = celu_fast(a);
            }
            x[0] = v0.x;  x[1] = v0.y;  x[2] = v0.z;  x[3] = v0.w;
            x[4] = v1.x;  x[5] = v1.y;  x[6] = v1.z;  x[7] = v1.w;
            x[8] = v2.x;  x[9] = v2.y;  x[10] = v2.z; x[11] = v2.w;
            x[12] = v3.x; x[13] = v3.y; x[14] = v3.z; x[15] = v3.w;
        } else {
#pragma unroll
            for (int c = 0; c < 16; c++) { h[c] = 0.0f; x[c] = 0.0f; }
        }
        uint32_t hp[8], xp[8];
#pragma unroll
        for (int j = 0; j < 8; j++) {
            hp[j] = pack_half2(h[2 * j], h[2 * j + 1]);
            xp[j] = pack_half2(x[2 * j], x[2 * j + 1]);
        }
        *(uint4*)(s_h[warp] + (uint32_t)e * PHP)      = make_uint4(hp[0], hp[1], hp[2], hp[3]);
        *(uint4*)(s_h[warp] + (uint32_t)e * PHP + 16) = make_uint4(hp[4], hp[5], hp[6], hp[7]);
        *(uint4*)(s_x[warp] + (uint32_t)e * PHP)      = make_uint4(xp[0], xp[1], xp[2], xp[3]);
        *(uint4*)(s_x[warp] + (uint32_t)e * PHP + 16) = make_uint4(xp[4], xp[5], xp[6], xp[7]);
    }
    __syncwarp();

    // ldmatrix patterns
    const uint32_t nRow = (uint32_t)((lane & 7) + ((lane & 16) ? 8 : 0));  // non-trans B (n rows)
    const uint32_t nCol = (lane & 8) ? 16u : 0u;
    const uint32_t tRow = (uint32_t)((lane & 7) + (((lane >> 3) & 1) << 3)); // trans B (k rows)
    const uint32_t tCol = ((lane >> 4) & 1) * 16;
    const int g = lane >> 2;
    const int q = lane & 3;

    for (int t = 0; t < tiles; t++) {
        uint32_t bH[4], bX[4];
        // H^T B-frags: non-trans ldmatrix of [e][c] rows (n = e, k = c)
        LDMATRIX_X4(bH[0], bH[1], bH[2], bH[3], shB + (t * 16 + nRow) * PHP + nCol);
        // X B-frags: trans ldmatrix of [e][c] rows (k = e, n = c)
        LDMATRIX_X4_T(bX[0], bX[1], bX[2], bX[3], sxB + (t * 16 + tRow) * PHP + tCol);

#pragma unroll
        for (int mt = 0; mt < 4; mt++) {
            float C1a[4] = {0.f, 0.f, 0.f, 0.f};
            float C1b[4] = {0.f, 0.f, 0.f, 0.f};
            MMA_FP16(C1a, aW2[mt], bH[0], bH[1]);   // e 0..7
            MMA_FP16(C1b, aW2[mt], bH[2], bH[3]);   // e 8..15
            uint32_t aM[4];
            aM[0] = pack_half2(celu_fast(C1a[0]), celu_fast(C1a[1]));
            aM[1] = pack_half2(celu_fast(C1a[2]), celu_fast(C1a[3]));
            aM[2] = pack_half2(celu_fast(C1b[0]), celu_fast(C1b[1]));
            aM[3] = pack_half2(celu_fast(C1b[2]), celu_fast(C1b[3]));
            MMA_FP16(P + mt * 8,     aM, bX[0], bX[1]);   // c 0..7
            MMA_FP16(P + mt * 8 + 4, aM, bX[2], bX[3]);   // c 8..15
        }
    }

    // ---- store P^T * inv with k' = m*16 + c ordering ----
    __half* dp = g_P_h + (size_t)n * 1024;
#pragma unroll
    for (int mt = 0; mt < 4; mt++) {
#pragma unroll
        for (int ch = 0; ch < 2; ch++) {
#pragma unroll
            for (int r2 = 0; r2 < 2; r2++) {
                float v0 = P[mt * 8 + ch * 4 + 2 * r2]     * inv;
                float v1 = P[mt * 8 + ch * 4 + 2 * r2 + 1] * inv;
                int m = mt * 16 + g + 8 * r2;
                int c = ch * 8 + 2 * q;
                *(uint32_t*)(dp + m * 16 + c) = pack_half2(v0, v1);
            }
        }
    }
}

// ---------------------------------------------------------------------------
// Kernel D: out = P @ W3 + b3. M=128/CTA, 256 thr, single-fp16 W3, 4-stage.
// ---------------------------------------------------------------------------
#define PITCH_B 80
#define OFF_A   0
#define OFF_B   10240
#define STAGE_BYTES 15360
#define GEMM_SMEM (4 * STAGE_BYTES)

__global__ __launch_bounds__(256) void gemm_mma(
    const float* __restrict__ b3,
    float* __restrict__ out)
{
    extern __shared__ char dsm[];
    const uint32_t sbase = smem_u32(dsm);

    const int tid  = threadIdx.x;
    const int warp = tid >> 5;
    const int lane = tid & 31;
    const int ctaM = blockIdx.x * 128;

    const char* A_g = (const char*)(g_P_h + (size_t)ctaM * 1024);
    const char* B_g = (const char*)g_W3T;

    auto issue_loads = [&](int kt, int s) {
        uint32_t base = sbase + s * STAGE_BYTES;
        const int kb = kt * 64;
#pragma unroll
        for (int i = 0; i < 2; i++) {
            int idx = tid + i * 256;              // A: 128 rows x 4 segs
            int row = idx >> 2, seg = idx & 3;
            uint32_t d = base + OFF_A + row * PITCH_B + seg * 16;
            cp16(d, A_g + (size_t)row * 2048 + kb + seg * 16);
        }
        {
            int row = tid >> 2, seg = tid & 3;    // B: 64 rows x 4 segs
            uint32_t d = base + OFF_B + row * PITCH_B + seg * 16;
            cp16(d, B_g + (size_t)row * 2048 + kb + seg * 16);
        }
    };

    float C[8][4];
#pragma unroll
    for (int nt = 0; nt < 8; nt++)
#pragma unroll
        for (int i = 0; i < 4; i++) C[nt][i] = 0.0f;

    const uint32_t aRow  = warp * 16 + (lane & 15);
    const uint32_t aColB = ((lane >> 4) & 1) * 16;
    const uint32_t bRow  = (lane & 7) + ((lane & 16) ? 8 : 0);
    const uint32_t bColB = (lane & 8) ? 16 : 0;

    issue_loads(0, 0); CP_COMMIT();
    issue_loads(1, 1); CP_COMMIT();
    issue_loads(2, 2); CP_COMMIT();

    for (int kt = 0; kt < 32; kt++) {
        CP_WAIT(2);
        __syncthreads();
        if (kt + 3 < 32) issue_loads(kt + 3, (kt + 3) & 3);
        CP_COMMIT();

        const uint32_t base = sbase + (kt & 3) * STAGE_BYTES;
#pragma unroll
        for (int ks = 0; ks < 2; ks++) {
            const uint32_t kOffB = ks * 32;
            uint32_t a[4];
            LDMATRIX_X4(a[0], a[1], a[2], a[3],
                        base + OFF_A + aRow * PITCH_B + kOffB + aColB);
#pragma unroll
            for (int p = 0; p < 4; p++) {
                uint32_t b0, b1, b2, b3r;
                uint32_t ba = base + OFF_B + (p * 16 + bRow) * PITCH_B + kOffB + bColB;
                LDMATRIX_X4(b0, b1, b2, b3r, ba);
                MMA_FP16(C[2 * p],     a, b0, b1);
                MMA_FP16(C[2 * p + 1], a, b2, b3r);
            }
        }
    }

    const int g  = lane >> 2;
    const int q2 = (lane & 3) * 2;
    const int rowBase = ctaM + warp * 16;
#pragma unroll
    for (int nt = 0; nt < 8; nt++) {
        const int col = nt * 8 + q2;
        float2 bb = *(const float2*)(b3 + col);
        float2 v0, v1;
        v0.x = C[nt][0] + bb.x;
        v0.y = C[nt][1] + bb.y;
        v1.x = C[nt][2] + bb.x;
        v1.y = C[nt][3] + bb.y;
        *(float2*)(out + (size_t)(rowBase + g) * COUT + col) = v0;
        *(float2*)(out + (size_t)(rowBase + g + 8) * COUT + col) = v1;
    }
}

// ---------------------------------------------------------------------------
extern "C" void kernel_launch(void* const* d_in, const int* in_sizes, int n_in,
                              void* d_out, int out_size) {
    const float* x_in      = (const float*)d_in[0];
    const float* pos_in    = (const float*)d_in[1];
    const float* pos_out   = (const float*)d_in[2];
    const int*   in_index  = (const int*)d_in[3];
    const int*   out_index = (const int*)d_in[4];
    const float* W1        = (const float*)d_in[5];
    const float* W2        = (const float*)d_in[6];
    const float* W3        = (const float*)d_in[7];
    const float* b3        = (const float*)d_in[8];
    float* out = (float*)d_out;

    cudaFuncSetAttribute(gemm_mma, cudaFuncAttributeMaxDynamicSharedMemorySize, GEMM_SMEM);

    aux_kernel<<<NB_OFF + NB_W3, 256>>>(out_index, W3);
    edge_tc_kernel<<<NPTS / 4, 128>>>(x_in, pos_in, pos_out, in_index, W1, W2);
    gemm_mma<<<NPTS / 128, 256, GEMM_SMEM>>>(b3, out);
}